// round 1
// baseline (speedup 1.0000x reference)
#include <cuda_runtime.h>

// UnalignmentLoss: min over 17x17 shifts of mean L1 between shifted x crop and
// fixed y center crop. x,y: (4,3,256,256) fp32. Crop 224x224, shifts 0..32 step 2.

#define NS   17          // shifts per axis
#define W_   256         // image width/height
#define CH_  224         // crop size
#define BC_  12          // B*C planes
#define TOLC 16
#define COUNT_F (602112.0f)   // 4*3*224*224

__device__ float g_acc[NS * NS];

__global__ void zero_kernel() {
    if (threadIdx.x < NS * NS) g_acc[threadIdx.x] = 0.0f;
}

// Grid: (7 row-chunks, 17 shift-rows i, 12 bc planes). Block: 256 threads, 8 warps.
// Each warp handles 4 output rows; per row it stages the full 256-float x image
// row in shared memory, holds 7 y values in registers (coalesced lane+32k), and
// accumulates all 17 column shifts into registers.
__global__ __launch_bounds__(256) void corr_kernel(const float* __restrict__ x,
                                                   const float* __restrict__ y) {
    const int warp = threadIdx.x >> 5;
    const int lane = threadIdx.x & 31;
    const int bc   = blockIdx.z;
    const int i    = blockIdx.y;      // shift-row index, absolute shift = 2*i
    const int i2   = i * 2;

    const float* xb = x + (size_t)bc * W_ * W_;
    const float* yb = y + (size_t)bc * W_ * W_;

    __shared__ float xs[8][W_];

    float acc[NS];
#pragma unroll
    for (int j = 0; j < NS; j++) acc[j] = 0.0f;

    const int r0 = blockIdx.x * 32 + warp * 4;

#pragma unroll 1
    for (int rr = 0; rr < 4; rr++) {
        const int r = r0 + rr;
        const float* xrow = xb + (size_t)(i2 + r) * W_;
        const float* yrow = yb + (size_t)(TOLC + r) * W_ + TOLC;

        // Stage x image row (all 256 cols) into this warp's shared row.
#pragma unroll
        for (int k = 0; k < 8; k++) xs[warp][lane + 32 * k] = xrow[lane + 32 * k];

        // y crop values for this lane's 7 columns (cc = lane + 32k).
        float yv[7];
#pragma unroll
        for (int k = 0; k < 7; k++) yv[k] = yrow[lane + 32 * k];

        __syncwarp();

#pragma unroll
        for (int j = 0; j < NS; j++) {
#pragma unroll
            for (int k = 0; k < 7; k++) {
                // xc[r][cc] for shift (2i,2j) = x[i2+r][2j + cc]
                acc[j] += fabsf(xs[warp][2 * j + lane + 32 * k] - yv[k]);
            }
        }
        __syncwarp();   // protect xs before next row's store
    }

    // Warp reduction: bfly-reduce each shift-column sum; lane j keeps column j.
    float mine = 0.0f;
#pragma unroll
    for (int j = 0; j < NS; j++) {
        float v = acc[j];
#pragma unroll
        for (int off = 16; off; off >>= 1) v += __shfl_xor_sync(0xffffffffu, v, off);
        if (lane == j) mine = v;
    }
    if (lane < NS) atomicAdd(&g_acc[i * NS + lane], mine);
}

__global__ void final_kernel(float* __restrict__ out) {
    const int lane = threadIdx.x;
    float v = 3.4e38f;
    for (int idx = lane; idx < NS * NS; idx += 32) v = fminf(v, g_acc[idx]);
#pragma unroll
    for (int off = 16; off; off >>= 1)
        v = fminf(v, __shfl_xor_sync(0xffffffffu, v, off));
    if (lane == 0) out[0] = v * (1.0f / COUNT_F);
}

extern "C" void kernel_launch(void* const* d_in, const int* in_sizes, int n_in,
                              void* d_out, int out_size) {
    (void)in_sizes; (void)n_in; (void)out_size;
    const float* x = (const float*)d_in[0];
    const float* y = (const float*)d_in[1];
    float* out = (float*)d_out;

    zero_kernel<<<1, 512>>>();
    dim3 grid(7, NS, BC_);
    corr_kernel<<<grid, 256>>>(x, y);
    final_kernel<<<1, 32>>>(out);
}

// round 4
// speedup vs baseline: 1.1621x; 1.1621x over previous
#include <cuda_runtime.h>
#include <cstdint>

// UnalignmentLoss: min over 17x17 shifts (step 2) of mean L1 between shifted
// x crop and fixed y center crop. x,y: (4,3,256,256) fp32, crop 224x224.
//
// One warp per (plane, shift-row i, 8-row chunk). Each lane owns 8 contiguous
// output columns; it loads a 40-float x window into registers once per row
// (10 swizzled conflict-free LDS.v2.b64) and slides it across all 17 column
// shifts with packed f32x2 adds. abs = 64-bit AND (ALU pipe, overlaps FMA).
// (Resubmission of R3 source — previous round died to a broker infra failure.)

#define NS    17
#define W_    256
#define TOLC  16
#define COUNT_F 602112.0f   // 4*3*224*224

__device__ float g_acc[NS * NS];   // zero at load; final_kernel restores 0

// ---- packed f32x2 helpers (uint64_t = b64 carrier) ----
__device__ __forceinline__ uint64_t f2add(uint64_t a, uint64_t b) {
    uint64_t r; asm("add.rn.f32x2 %0, %1, %2;" : "=l"(r) : "l"(a), "l"(b)); return r;
}
__device__ __forceinline__ uint64_t f2abs(uint64_t a) {
    return a & 0x7FFFFFFF7FFFFFFFULL;
}
__device__ __forceinline__ uint64_t pack2(float lo, float hi) {
    uint64_t r; asm("mov.b64 %0, {%1, %2};" : "=l"(r) : "f"(lo), "f"(hi)); return r;
}
__device__ __forceinline__ void unpack2(uint64_t v, float& lo, float& hi) {
    asm("mov.b64 {%0, %1}, %2;" : "=f"(lo), "=f"(hi) : "l"(v));
}
__device__ __forceinline__ void sts128(unsigned addr, float4 v) {
    asm volatile("st.shared.v4.f32 [%0], {%1,%2,%3,%4};"
                 :: "r"(addr), "f"(v.x), "f"(v.y), "f"(v.z), "f"(v.w));
}
__device__ __forceinline__ void lds_2b64(unsigned addr, uint64_t& a, uint64_t& b) {
    asm volatile("ld.shared.v2.b64 {%0,%1}, [%2];" : "=l"(a), "=l"(b) : "r"(addr));
}
// XOR swizzle on 16B granule index (row = 64 granules): conflict-free for the
// 2-granule staging stores and the 10-granule strided window reads.
__device__ __forceinline__ int swz(int t) { return t ^ ((t >> 3) & 7); }

__global__ __launch_bounds__(128) void corr_kernel(const float* __restrict__ x,
                                                   const float* __restrict__ y) {
    const int warp = threadIdx.x >> 5;
    const int lane = threadIdx.x & 31;
    const int bc   = blockIdx.z;       // plane
    const int i    = blockIdx.y;       // shift-row index (shift = 2*i)
    const int r0   = blockIdx.x * 32 + warp * 8;

    const float* xb = x + (size_t)bc * (W_ * W_);
    const float* yb = y + (size_t)bc * (W_ * W_);

    __shared__ __align__(16) float xs[4][2][W_];   // [warp][double-buffer][256]

    const unsigned base = (unsigned)__cvta_generic_to_shared(&xs[warp][0][0]);

    const int Lc = lane < 28 ? lane : 27;          // idle lanes: broadcast reads
    unsigned roff[10];
#pragma unroll
    for (int m = 0; m < 10; m++) roff[m] = (unsigned)(swz(2 * Lc + m) * 16);
    const unsigned s0 = (unsigned)(swz(2 * lane)     * 16);
    const unsigned s1 = (unsigned)(swz(2 * lane + 1) * 16);

    uint64_t acc[NS];
#pragma unroll
    for (int j = 0; j < NS; j++) acc[j] = 0ull;    // +0.0f,+0.0f

    // Prefetch x row 0.
    const float4* xrow = (const float4*)(xb + (size_t)(2 * i + r0) * W_);
    float4 xa = xrow[2 * lane];
    float4 xc = xrow[2 * lane + 1];

#pragma unroll 1
    for (int rr = 0; rr < 8; rr++) {
        const unsigned boff = (rr & 1) ? (unsigned)(W_ * 4) : 0u;
        sts128(base + boff + s0, xa);
        sts128(base + boff + s1, xc);

        // y crop row (16B-aligned: (16+r)*256+16 floats).
        const float4* yrow = (const float4*)(yb + (size_t)(TOLC + r0 + rr) * W_ + TOLC);
        float4 ya = yrow[2 * lane];
        float4 yc = yrow[2 * lane + 1];

        if (rr < 7) {   // prefetch next x row while this one is staged
            const float4* xn = (const float4*)(xb + (size_t)(2 * i + r0 + rr + 1) * W_);
            xa = xn[2 * lane];
            xc = xn[2 * lane + 1];
        }

        const uint64_t ny0 = pack2(-ya.x, -ya.y);
        const uint64_t ny1 = pack2(-ya.z, -ya.w);
        const uint64_t ny2 = pack2(-yc.x, -yc.y);
        const uint64_t ny3 = pack2(-yc.z, -yc.w);

        __syncwarp();

        uint64_t wd[20];   // 40-float window x[8L .. 8L+40) as 20 f32x2 pairs
#pragma unroll
        for (int m = 0; m < 10; m++)
            lds_2b64(base + boff + roff[m], wd[2 * m], wd[2 * m + 1]);

#pragma unroll
        for (int j = 0; j < NS; j++) {
            uint64_t a0 = f2abs(f2add(wd[j + 0], ny0));
            uint64_t a1 = f2abs(f2add(wd[j + 1], ny1));
            uint64_t a2 = f2abs(f2add(wd[j + 2], ny2));
            uint64_t a3 = f2abs(f2add(wd[j + 3], ny3));
            acc[j] = f2add(acc[j], f2add(f2add(a0, a1), f2add(a2, a3)));
        }
    }

    // Reduce: lane j keeps shift-column j's warp sum; idle lanes contribute 0.
    float keep = 0.0f;
#pragma unroll
    for (int j = 0; j < NS; j++) {
        float lo, hi; unpack2(acc[j], lo, hi);
        float v = (lane < 28) ? (lo + hi) : 0.0f;
#pragma unroll
        for (int off = 16; off; off >>= 1) v += __shfl_xor_sync(0xffffffffu, v, off);
        if (lane == j) keep = v;
    }
    if (lane < NS) atomicAdd(&g_acc[i * NS + lane], keep);
}

__global__ void final_kernel(float* __restrict__ out) {
    const int lane = threadIdx.x;
    float v = 3.4e38f;
    for (int idx = lane; idx < NS * NS; idx += 32) v = fminf(v, g_acc[idx]);
    __syncwarp();
    for (int idx = lane; idx < NS * NS; idx += 32) g_acc[idx] = 0.0f;  // restore invariant
#pragma unroll
    for (int off = 16; off; off >>= 1)
        v = fminf(v, __shfl_xor_sync(0xffffffffu, v, off));
    if (lane == 0) out[0] = v * (1.0f / COUNT_F);
}

extern "C" void kernel_launch(void* const* d_in, const int* in_sizes, int n_in,
                              void* d_out, int out_size) {
    (void)in_sizes; (void)n_in; (void)out_size;
    const float* x = (const float*)d_in[0];
    const float* y = (const float*)d_in[1];
    float* out = (float*)d_out;

    dim3 grid(7, NS, 12);
    corr_kernel<<<grid, 128>>>(x, y);
    final_kernel<<<1, 32>>>(out);
}